// round 7
// baseline (speedup 1.0000x reference)
#include <cuda_runtime.h>
#include <cuda_bf16.h>
#include <math.h>
#include <stdint.h>

// ---------------------------------------------------------------------------
// GCN: out[1,64] = max_n( tanh(GCN2( tanh(GCN1(x)) @ Wl + bl )) @ Wo + bo )
// GCNConv(x) = scatter_{dst}( (x@W)[src] * dinv[src]*dinv[dst] ) + selfloop + b
//
// Strategy:
//  - CSR by dst (counting sort) -> atomic-free warp-per-node gather.
//  - dinv[src] folded into GEMM epilogue (row-scaled output).
//  - (V@Wl + bl)@W2 = V@(Wl@W2) + bl@W2 -> precompute Wc, bc (kills one GEMM).
//  - GEMM: 128x128 tile, 8x8 micro-tile, double-buffered smem, packed
//    fp32x2 FMAs (fma.rn.f32x2 -> FFMA2, 2 FLOPs/lane/instr, exact fp32).
// ---------------------------------------------------------------------------

#define MAX_N 50000
#define MAX_E 800000
#define FDIM  128
#define CHUNK 16

// device scratch (no allocations allowed)
__device__ float g_U[MAX_N * FDIM];
__device__ float g_V[MAX_N * FDIM];
__device__ int   g_deg[MAX_N];
__device__ float g_dinv[MAX_N];
__device__ int   g_rowptr[MAX_N + 1];
__device__ int   g_cursor[MAX_N];
__device__ int   g_esrc[MAX_E];
__device__ float g_Wc[FDIM * FDIM];
__device__ float g_bc[FDIM];

// ---- packed fp32x2 helpers -------------------------------------------------
__device__ __forceinline__ unsigned long long pack2_dup(float x) {
    unsigned long long r;
    asm("mov.b64 %0, {%1, %1};" : "=l"(r) : "f"(x));
    return r;
}
__device__ __forceinline__ void fma2(unsigned long long& d,
                                     unsigned long long a, unsigned long long b) {
    asm("fma.rn.f32x2 %0, %1, %2, %3;" : "=l"(d) : "l"(a), "l"(b), "l"(d));
}
__device__ __forceinline__ void unpack2(unsigned long long v, float& lo, float& hi) {
    asm("mov.b64 {%0, %1}, %2;" : "=f"(lo), "=f"(hi) : "l"(v));
}

// ---------------------------------------------------------------------------
__global__ void zero_i(int* __restrict__ p, int n) {
    int i = blockIdx.x * blockDim.x + threadIdx.x;
    if (i < n) p[i] = 0;
}

__global__ void deg_count(const int* __restrict__ dst, int E, int* __restrict__ deg) {
    int e = blockIdx.x * blockDim.x + threadIdx.x;
    if (e < E) atomicAdd(&deg[dst[e]], 1);
}

__global__ void compute_dinv(const int* __restrict__ deg, float* __restrict__ dinv, int N) {
    int i = blockIdx.x * blockDim.x + threadIdx.x;
    if (i < N) dinv[i] = rsqrtf((float)deg[i] + 1.0f);  // +1 self loop
}

// Single-block exclusive scan over deg -> row_ptr (N up to 50000).
__global__ void exscan_rowptr(const int* __restrict__ deg, int* __restrict__ row_ptr,
                              int* __restrict__ cursor, int N) {
    __shared__ int sums[1024];
    const int t = threadIdx.x;
    const int chunk = (N + 1023) / 1024;
    const int start = t * chunk;
    const int end = min(start + chunk, N);

    int s = 0;
    for (int i = start; i < end; i++) s += deg[i];
    sums[t] = s;
    __syncthreads();
    for (int off = 1; off < 1024; off <<= 1) {
        int v = (t >= off) ? sums[t - off] : 0;
        __syncthreads();
        sums[t] += v;
        __syncthreads();
    }
    int base = (t > 0) ? sums[t - 1] : 0;
    for (int i = start; i < end; i++) {
        row_ptr[i] = base;
        cursor[i] = base;
        base += deg[i];
    }
    if (t == 1023) row_ptr[N] = sums[1023];
}

__global__ void bucket_fill(const int* __restrict__ src, const int* __restrict__ dst,
                            int E, int* __restrict__ cursor, int* __restrict__ esrc) {
    int e = blockIdx.x * blockDim.x + threadIdx.x;
    if (e >= E) return;
    int d = dst[e];
    int pos = atomicAdd(&cursor[d], 1);
    esrc[pos] = src[e];
}

// ---------------------------------------------------------------------------
// Combine weights: Wc = Wl @ W2  (128x128), bc = bl @ W2 (128).
// ---------------------------------------------------------------------------
__global__ void combine_w(const float* __restrict__ Wl, const float* __restrict__ bl,
                          const float* __restrict__ W2,
                          float* __restrict__ Wc, float* __restrict__ bc) {
    __shared__ float rowv[FDIM];
    const int i = blockIdx.x;       // 0..128 (128 == bias row)
    const int j = threadIdx.x;      // 0..127
    const float* vec = (i < FDIM) ? (Wl + i * FDIM) : bl;
    rowv[j] = vec[j];
    __syncthreads();
    float acc = 0.f;
#pragma unroll 8
    for (int k = 0; k < FDIM; k++)
        acc = fmaf(rowv[k], __ldg(&W2[k * FDIM + j]), acc);
    if (i < FDIM) Wc[i * FDIM + j] = acc;
    else          bc[j] = acc;
}

// ---------------------------------------------------------------------------
// SGEMM: C[N,128] = ((A[N,128] @ W[128,128]) + bias) * rowscale[row].
// Block tile 128x128, 256 threads, micro-tile 8x8, double-buffered K chunk 16,
// packed fp32x2 inner product (FFMA2).
// ---------------------------------------------------------------------------
__global__ void __launch_bounds__(256) gemm128(
        const float* __restrict__ A, const float* __restrict__ W,
        const float* __restrict__ bias, const float* __restrict__ rowscale,
        float* __restrict__ C, int N) {
    __shared__ __align__(16) float As[2][128][CHUNK + 1];
    __shared__ __align__(16) float Bs[2][CHUNK][128];
    const int tid  = threadIdx.x;
    const int rowt = tid >> 4;        // 0..15 -> rows rowt*8 .. +7
    const int colt = tid & 15;        // 0..15 -> cols colt*8 .. +7
    const int rowBase = blockIdx.x * 128;

    // loader mapping (per K chunk): A tile 128x16 = 2048 floats, 8 per thread
    const int la_r  = (tid * 8) >> 4;          // 0..127  (two float4 in same row)
    const int la_k  = (tid * 8) & 15;          // 0 or 8
    const int larow = rowBase + la_r;
    // B tile 16x128 = 2048 floats, 8 per thread
    const int lb_k  = (tid * 8) >> 7;          // 0..15
    const int lb_c  = (tid * 8) & 127;         // multiple of 8

    // acc2[r][p] holds C columns (colt*8 + 2p, colt*8 + 2p + 1) for row r.
    unsigned long long acc2[8][4];
#pragma unroll
    for (int r = 0; r < 8; r++)
#pragma unroll
        for (int p = 0; p < 4; p++) acc2[r][p] = 0ull;

    // ---- prologue: load chunk 0 into buffer 0 ------------------------------
    {
        float4 a0 = make_float4(0.f, 0.f, 0.f, 0.f), a1 = a0;
        if (larow < N) {
            a0 = *(const float4*)(A + (size_t)larow * 128 + la_k + 0);
            a1 = *(const float4*)(A + (size_t)larow * 128 + la_k + 4);
        }
        As[0][la_r][la_k + 0] = a0.x; As[0][la_r][la_k + 1] = a0.y;
        As[0][la_r][la_k + 2] = a0.z; As[0][la_r][la_k + 3] = a0.w;
        As[0][la_r][la_k + 4] = a1.x; As[0][la_r][la_k + 5] = a1.y;
        As[0][la_r][la_k + 6] = a1.z; As[0][la_r][la_k + 7] = a1.w;
        float4 b0 = *(const float4*)(W + (size_t)lb_k * 128 + lb_c + 0);
        float4 b1 = *(const float4*)(W + (size_t)lb_k * 128 + lb_c + 4);
        *(float4*)&Bs[0][lb_k][lb_c + 0] = b0;
        *(float4*)&Bs[0][lb_k][lb_c + 4] = b1;
    }
    __syncthreads();

    // ---- main loop: 8 chunks, ping-pong ------------------------------------
#pragma unroll
    for (int ch = 0; ch < 8; ch++) {
        const int cur = ch & 1;
        const int nxt = cur ^ 1;
        float4 pa0, pa1, pb0, pb1;
        if (ch < 7) {
            const int k0 = (ch + 1) * CHUNK;
            pa0 = make_float4(0.f, 0.f, 0.f, 0.f); pa1 = pa0;
            if (larow < N) {
                pa0 = *(const float4*)(A + (size_t)larow * 128 + k0 + la_k + 0);
                pa1 = *(const float4*)(A + (size_t)larow * 128 + k0 + la_k + 4);
            }
            pb0 = *(const float4*)(W + (size_t)(k0 + lb_k) * 128 + lb_c + 0);
            pb1 = *(const float4*)(W + (size_t)(k0 + lb_k) * 128 + lb_c + 4);
        }

#pragma unroll
        for (int kk = 0; kk < CHUNK; kk++) {
            unsigned long long b2[4];
#pragma unroll
            for (int p = 0; p < 4; p++)
                b2[p] = *(const unsigned long long*)&Bs[cur][kk][colt * 8 + p * 2];
#pragma unroll
            for (int r = 0; r < 8; r++) {
                unsigned long long a2 = pack2_dup(As[cur][rowt * 8 + r][kk]);
#pragma unroll
                for (int p = 0; p < 4; p++) fma2(acc2[r][p], a2, b2[p]);
            }
        }

        if (ch < 7) {
            As[nxt][la_r][la_k + 0] = pa0.x; As[nxt][la_r][la_k + 1] = pa0.y;
            As[nxt][la_r][la_k + 2] = pa0.z; As[nxt][la_r][la_k + 3] = pa0.w;
            As[nxt][la_r][la_k + 4] = pa1.x; As[nxt][la_r][la_k + 5] = pa1.y;
            As[nxt][la_r][la_k + 6] = pa1.z; As[nxt][la_r][la_k + 7] = pa1.w;
            *(float4*)&Bs[nxt][lb_k][lb_c + 0] = pb0;
            *(float4*)&Bs[nxt][lb_k][lb_c + 4] = pb1;
            __syncthreads();
        }
    }

    // ---- epilogue ----------------------------------------------------------
    float4 bv0 = make_float4(0.f, 0.f, 0.f, 0.f), bv1 = bv0;
    if (bias) {
        bv0 = *(const float4*)(bias + colt * 8 + 0);
        bv1 = *(const float4*)(bias + colt * 8 + 4);
    }
#pragma unroll
    for (int r = 0; r < 8; r++) {
        int grow = rowBase + rowt * 8 + r;
        if (grow >= N) continue;
        float sc = rowscale ? __ldg(&rowscale[grow]) : 1.0f;
        float* cp = C + (size_t)grow * 128 + colt * 8;
        float a0, a1, a2v, a3, a4, a5, a6, a7;
        unpack2(acc2[r][0], a0, a1);
        unpack2(acc2[r][1], a2v, a3);
        unpack2(acc2[r][2], a4, a5);
        unpack2(acc2[r][3], a6, a7);
        float4 v0, v1;
        v0.x = (a0 + bv0.x) * sc; v0.y = (a1 + bv0.y) * sc;
        v0.z = (a2v + bv0.z) * sc; v0.w = (a3 + bv0.w) * sc;
        v1.x = (a4 + bv1.x) * sc; v1.y = (a5 + bv1.y) * sc;
        v1.z = (a6 + bv1.z) * sc; v1.w = (a7 + bv1.w) * sc;
        *(float4*)(cp + 0) = v0;
        *(float4*)(cp + 4) = v1;
    }
}

// ---------------------------------------------------------------------------
// Gather (atomic-free GCN aggregate), fused self-loop + bias + tanh.
// Input h is already scaled by dinv[src] (GEMM epilogue).
//   out[d] = tanh( (h[d] + sum_{s in in(d)} h[s]) * dinv[d] + b )
// One warp per dst node; lane owns 4 feature floats.
// ---------------------------------------------------------------------------
__global__ void gather_tanh(const float* __restrict__ h, const int* __restrict__ row_ptr,
                            const int* __restrict__ esrc, const float* __restrict__ dinv,
                            const float* __restrict__ b, float* __restrict__ out, int N) {
    int warp = (blockIdx.x * blockDim.x + threadIdx.x) >> 5;
    if (warp >= N) return;
    int lane = threadIdx.x & 31;

    const int beg = __ldg(&row_ptr[warp]);
    const int end = __ldg(&row_ptr[warp + 1]);
    const float di = __ldg(&dinv[warp]);

    float4 acc = *(const float4*)(h + (size_t)warp * 128 + lane * 4);

    int e = beg;
    for (; e + 3 < end; e += 4) {
        int s0 = __ldg(&esrc[e]);
        int s1 = __ldg(&esrc[e + 1]);
        int s2 = __ldg(&esrc[e + 2]);
        int s3 = __ldg(&esrc[e + 3]);
        float4 v0 = *(const float4*)(h + (size_t)s0 * 128 + lane * 4);
        float4 v1 = *(const float4*)(h + (size_t)s1 * 128 + lane * 4);
        float4 v2 = *(const float4*)(h + (size_t)s2 * 128 + lane * 4);
        float4 v3 = *(const float4*)(h + (size_t)s3 * 128 + lane * 4);
        acc.x += v0.x + v1.x + v2.x + v3.x;
        acc.y += v0.y + v1.y + v2.y + v3.y;
        acc.z += v0.z + v1.z + v2.z + v3.z;
        acc.w += v0.w + v1.w + v2.w + v3.w;
    }
    for (; e < end; e++) {
        int s0 = __ldg(&esrc[e]);
        float4 v0 = *(const float4*)(h + (size_t)s0 * 128 + lane * 4);
        acc.x += v0.x; acc.y += v0.y; acc.z += v0.z; acc.w += v0.w;
    }

    const float4 bb = *(const float4*)(b + lane * 4);
    float4 o;
    o.x = tanhf(fmaf(acc.x, di, bb.x));
    o.y = tanhf(fmaf(acc.y, di, bb.y));
    o.z = tanhf(fmaf(acc.z, di, bb.z));
    o.w = tanhf(fmaf(acc.w, di, bb.w));
    *(float4*)(out + (size_t)warp * 128 + lane * 4) = o;
}

// ---------------------------------------------------------------------------
// Final: out[j] = max_n ( h[n] @ Wo[:,j] ) + bo[j],   Wo [128,64]
// ---------------------------------------------------------------------------
__device__ __forceinline__ void atomicMaxF(float* addr, float v) {
    if (v >= 0.f) atomicMax((int*)addr, __float_as_int(v));
    else          atomicMin((unsigned int*)addr, __float_as_uint(v));
}

__global__ void init_out(float* out, int n) {
    int i = blockIdx.x * blockDim.x + threadIdx.x;
    if (i < n) out[i] = -INFINITY;
}

__global__ void final_max(const float* __restrict__ h, const float* __restrict__ Wo,
                          const float* __restrict__ bo, float* __restrict__ out, int N) {
    int lane   = threadIdx.x & 31;
    int warpId = (blockIdx.x * blockDim.x + threadIdx.x) >> 5;
    int nwarps = (gridDim.x * blockDim.x) >> 5;
    float m0 = -INFINITY, m1 = -INFINITY;

    for (int base = warpId * 4; base < N; base += nwarps * 4) {
        float4 hr[4];
#pragma unroll
        for (int r = 0; r < 4; r++) {
            int n = base + r;
            if (n >= N) n = N - 1;  // duplicate is harmless under max
            hr[r] = *(const float4*)(h + (size_t)n * 128 + lane * 4);
        }
        float a[8];
#pragma unroll
        for (int i = 0; i < 8; i++) a[i] = 0.f;
#pragma unroll
        for (int l = 0; l < 32; l++) {
            float hb[4][4];
#pragma unroll
            for (int r = 0; r < 4; r++) {
                hb[r][0] = __shfl_sync(0xffffffffu, hr[r].x, l);
                hb[r][1] = __shfl_sync(0xffffffffu, hr[r].y, l);
                hb[r][2] = __shfl_sync(0xffffffffu, hr[r].z, l);
                hb[r][3] = __shfl_sync(0xffffffffu, hr[r].w, l);
            }
#pragma unroll
            for (int c = 0; c < 4; c++) {
                int k = l * 4 + c;
                float w0 = __ldg(&Wo[k * 64 + lane]);
                float w1 = __ldg(&Wo[k * 64 + lane + 32]);
#pragma unroll
                for (int r = 0; r < 4; r++) {
                    a[r]     = fmaf(hb[r][c], w0, a[r]);
                    a[4 + r] = fmaf(hb[r][c], w1, a[4 + r]);
                }
            }
        }
#pragma unroll
        for (int r = 0; r < 4; r++) {
            m0 = fmaxf(m0, a[r]);
            m1 = fmaxf(m1, a[4 + r]);
        }
    }
    m0 += __ldg(&bo[lane]);
    m1 += __ldg(&bo[lane + 32]);
    atomicMaxF(&out[lane], m0);
    atomicMaxF(&out[lane + 32], m1);
}

// ---------------------------------------------------------------------------
extern "C" void kernel_launch(void* const* d_in, const int* in_sizes, int n_in,
                              void* d_out, int out_size) {
    const float* x  = (const float*)d_in[0];
    const int*   ei = (const int*)  d_in[1];
    const float* W1 = (const float*)d_in[2];
    const float* b1 = (const float*)d_in[3];
    const float* Wl = (const float*)d_in[4];
    const float* bl = (const float*)d_in[5];
    const float* W2 = (const float*)d_in[6];
    const float* b2 = (const float*)d_in[7];
    const float* Wo = (const float*)d_in[8];
    const float* bo = (const float*)d_in[9];
    float* out = (float*)d_out;

    const int N = in_sizes[0] / 128;
    const int E = in_sizes[1] / 2;
    const int* src = ei;
    const int* dst = ei + E;

    float *U, *V, *dinv, *Wc, *bc;
    int *deg, *rowptr, *cursor, *esrc;
    cudaGetSymbolAddress((void**)&U,      g_U);
    cudaGetSymbolAddress((void**)&V,      g_V);
    cudaGetSymbolAddress((void**)&deg,    g_deg);
    cudaGetSymbolAddress((void**)&dinv,   g_dinv);
    cudaGetSymbolAddress((void**)&rowptr, g_rowptr);
    cudaGetSymbolAddress((void**)&cursor, g_cursor);
    cudaGetSymbolAddress((void**)&esrc,   g_esrc);
    cudaGetSymbolAddress((void**)&Wc,     g_Wc);
    cudaGetSymbolAddress((void**)&bc,     g_bc);

    const int T = 256;

    // ---- CSR build + weight combine ----------------------------------------
    zero_i<<<(N + T - 1) / T, T>>>(deg, N);
    deg_count<<<(E + T - 1) / T, T>>>(dst, E, deg);
    compute_dinv<<<(N + T - 1) / T, T>>>(deg, dinv, N);
    exscan_rowptr<<<1, 1024>>>(deg, rowptr, cursor, N);
    bucket_fill<<<(E + T - 1) / T, T>>>(src, dst, E, cursor, esrc);
    combine_w<<<FDIM + 1, FDIM>>>(Wl, bl, W2, Wc, bc);   // Wc = Wl@W2, bc = bl@W2

    const int gatherBlocks = (N * 32 + T - 1) / T;
    const int gemmBlocks = (N + 127) / 128;

    // ---- layer 1: U = (x @ W1) * dinv ; V = tanh(gather(U)*dinv + b1) -------
    gemm128<<<gemmBlocks, T>>>(x, W1, nullptr, dinv, U, N);
    gather_tanh<<<gatherBlocks, T>>>(U, rowptr, esrc, dinv, b1, V, N);

    // ---- fused linear+layer2 pre-GEMM: U = (V@Wc + bc) * dinv ---------------
    gemm128<<<gemmBlocks, T>>>(V, Wc, bc, dinv, U, N);
    gather_tanh<<<gatherBlocks, T>>>(U, rowptr, esrc, dinv, b2, V, N);

    // ---- output: out = max_n( V @ Wo ) + bo --------------------------------
    init_out<<<1, 64>>>(out, out_size);
    final_max<<<592, T>>>(V, Wo, bo, out, N);
}

// round 12
// speedup vs baseline: 1.2316x; 1.2316x over previous
#include <cuda_runtime.h>
#include <cuda_bf16.h>
#include <math.h>
#include <stdint.h>

// ---------------------------------------------------------------------------
// GCN: out[1,64] = max_n( tanh(GCN2( tanh(GCN1(x)) @ Wl + bl )) @ Wo + bo )
// GCNConv(x) = scatter_{dst}( (x@W)[src] * dinv[src]*dinv[dst] ) + selfloop + b
//
// Strategy:
//  - CSR by dst (counting sort) -> atomic-free warp-per-node gather (MLP=8).
//  - dinv[src] folded into GEMM epilogue (row-scaled output).
//  - (V@Wl + bl)@W2 = V@(Wl@W2) + bl@W2 -> precompute Wc, bc (kills one GEMM).
//  - GEMM: 128x128 tile, 8x8 micro-tile, double-buffered smem, FFMA2.
//  - 3-pass parallel prefix scan for rowptr (R7: single-block scan was 71.8us).
// ---------------------------------------------------------------------------

#define MAX_N 50000
#define MAX_E 800000
#define FDIM  128
#define CHUNK 16
#define STILE 1024                      // nodes per scan tile (256 thr x 4)
#define MAX_TILES 64                    // ceil(50000/1024)=49 <= 64

// device scratch (no allocations allowed)
__device__ float g_U[MAX_N * FDIM];
__device__ float g_V[MAX_N * FDIM];
__device__ int   g_deg[MAX_N];
__device__ float g_dinv[MAX_N];
__device__ int   g_rowptr[MAX_N + 1];
__device__ int   g_cursor[MAX_N];
__device__ int   g_esrc[MAX_E];
__device__ float g_Wc[FDIM * FDIM];
__device__ float g_bc[FDIM];
__device__ int   g_tilesum[MAX_TILES];
__device__ int   g_tileoff[MAX_TILES];

// ---- packed fp32x2 helpers -------------------------------------------------
__device__ __forceinline__ unsigned long long pack2_dup(float x) {
    unsigned long long r;
    asm("mov.b64 %0, {%1, %1};" : "=l"(r) : "f"(x));
    return r;
}
__device__ __forceinline__ void fma2(unsigned long long& d,
                                     unsigned long long a, unsigned long long b) {
    asm("fma.rn.f32x2 %0, %1, %2, %3;" : "=l"(d) : "l"(a), "l"(b), "l"(d));
}
__device__ __forceinline__ void unpack2(unsigned long long v, float& lo, float& hi) {
    asm("mov.b64 {%0, %1}, %2;" : "=f"(lo), "=f"(hi) : "l"(v));
}

// ---------------------------------------------------------------------------
__global__ void zero_i(int* __restrict__ p, int n) {
    int i = blockIdx.x * blockDim.x + threadIdx.x;
    if (i < n) p[i] = 0;
}

__global__ void deg_count(const int* __restrict__ dst, int E, int* __restrict__ deg) {
    int e = blockIdx.x * blockDim.x + threadIdx.x;
    if (e < E) atomicAdd(&deg[dst[e]], 1);
}

// ---------------------------------------------------------------------------
// Pass A: per-tile exclusive scan of deg into rowptr (local values), tile sums.
// ---------------------------------------------------------------------------
__global__ void scan_local(const int* __restrict__ deg, int* __restrict__ rp,
                           int* __restrict__ tilesum, int N) {
    const int tid  = threadIdx.x;
    const int lane = tid & 31, wid = tid >> 5;
    const int base = blockIdx.x * STILE + tid * 4;

    int d0 = 0, d1 = 0, d2 = 0, d3 = 0;
    if (base + 3 < N) {
        int4 v = *(const int4*)(deg + base);
        d0 = v.x; d1 = v.y; d2 = v.z; d3 = v.w;
    } else {
        if (base + 0 < N) d0 = deg[base + 0];
        if (base + 1 < N) d1 = deg[base + 1];
        if (base + 2 < N) d2 = deg[base + 2];
        if (base + 3 < N) d3 = deg[base + 3];
    }
    const int s = d0 + d1 + d2 + d3;

    int incl = s;
#pragma unroll
    for (int o = 1; o < 32; o <<= 1) {
        int v = __shfl_up_sync(0xffffffffu, incl, o);
        if (lane >= o) incl += v;
    }
    __shared__ int wsum[8];
    if (lane == 31) wsum[wid] = incl;
    __syncthreads();
    int wbase = 0;
#pragma unroll
    for (int w = 0; w < 8; w++) if (w < wid) wbase += wsum[w];

    const int texcl = wbase + incl - s;
    if (base + 0 < N) rp[base + 0] = texcl;
    if (base + 1 < N) rp[base + 1] = texcl + d0;
    if (base + 2 < N) rp[base + 2] = texcl + d0 + d1;
    if (base + 3 < N) rp[base + 3] = texcl + d0 + d1 + d2;
    if (tid == 255) tilesum[blockIdx.x] = texcl + s;
}

// ---------------------------------------------------------------------------
// Pass B: exclusive scan of <=64 tile sums (1 block, 64 threads, 2 warps).
// Also writes rowptr[N] = grand total.
// ---------------------------------------------------------------------------
__global__ void scan_tiles(const int* __restrict__ tilesum, int* __restrict__ tileoff,
                           int* __restrict__ rp, int ntiles, int N) {
    const int tid = threadIdx.x;           // 0..63
    const int lane = tid & 31, wid = tid >> 5;
    int v = (tid < ntiles) ? tilesum[tid] : 0;
    int incl = v;
#pragma unroll
    for (int o = 1; o < 32; o <<= 1) {
        int t = __shfl_up_sync(0xffffffffu, incl, o);
        if (lane >= o) incl += t;
    }
    __shared__ int w0tot;
    if (wid == 0 && lane == 31) w0tot = incl;
    __syncthreads();
    const int b = (wid == 1) ? w0tot : 0;
    tileoff[tid] = b + incl - v;
    if (tid == 63) rp[N] = b + incl;
}

// ---------------------------------------------------------------------------
// Pass C: rowptr[i] += tileoff[tile]; cursor[i] = rowptr[i]; dinv[i] fused.
// ---------------------------------------------------------------------------
__global__ void apply_off(int* __restrict__ rp, int* __restrict__ cursor,
                          const int* __restrict__ tileoff,
                          const int* __restrict__ deg, float* __restrict__ dinv, int N) {
    int i = blockIdx.x * blockDim.x + threadIdx.x;
    if (i >= N) return;
    int r = rp[i] + __ldg(&tileoff[i >> 10]);
    rp[i] = r;
    cursor[i] = r;
    dinv[i] = rsqrtf((float)__ldg(&deg[i]) + 1.0f);   // +1 self loop
}

__global__ void bucket_fill(const int* __restrict__ src, const int* __restrict__ dst,
                            int E, int* __restrict__ cursor, int* __restrict__ esrc) {
    int e = blockIdx.x * blockDim.x + threadIdx.x;
    if (e >= E) return;
    int d = dst[e];
    int pos = atomicAdd(&cursor[d], 1);
    esrc[pos] = src[e];
}

// ---------------------------------------------------------------------------
// Combine weights: Wc = Wl @ W2  (128x128), bc = bl @ W2 (128).
// ---------------------------------------------------------------------------
__global__ void combine_w(const float* __restrict__ Wl, const float* __restrict__ bl,
                          const float* __restrict__ W2,
                          float* __restrict__ Wc, float* __restrict__ bc) {
    __shared__ float rowv[FDIM];
    const int i = blockIdx.x;       // 0..128 (128 == bias row)
    const int j = threadIdx.x;      // 0..127
    const float* vec = (i < FDIM) ? (Wl + i * FDIM) : bl;
    rowv[j] = vec[j];
    __syncthreads();
    float acc = 0.f;
#pragma unroll 8
    for (int k = 0; k < FDIM; k++)
        acc = fmaf(rowv[k], __ldg(&W2[k * FDIM + j]), acc);
    if (i < FDIM) Wc[i * FDIM + j] = acc;
    else          bc[j] = acc;
}

// ---------------------------------------------------------------------------
// SGEMM: C[N,128] = ((A[N,128] @ W[128,128]) + bias) * rowscale[row].
// Block tile 128x128, 256 threads, micro-tile 8x8, double-buffered K chunk 16,
// packed fp32x2 inner product (FFMA2).
// ---------------------------------------------------------------------------
__global__ void __launch_bounds__(256) gemm128(
        const float* __restrict__ A, const float* __restrict__ W,
        const float* __restrict__ bias, const float* __restrict__ rowscale,
        float* __restrict__ C, int N) {
    __shared__ __align__(16) float As[2][128][CHUNK + 1];
    __shared__ __align__(16) float Bs[2][CHUNK][128];
    const int tid  = threadIdx.x;
    const int rowt = tid >> 4;        // 0..15 -> rows rowt*8 .. +7
    const int colt = tid & 15;        // 0..15 -> cols colt*8 .. +7
    const int rowBase = blockIdx.x * 128;

    const int la_r  = (tid * 8) >> 4;          // 0..127
    const int la_k  = (tid * 8) & 15;          // 0 or 8
    const int larow = rowBase + la_r;
    const int lb_k  = (tid * 8) >> 7;          // 0..15
    const int lb_c  = (tid * 8) & 127;         // multiple of 8

    unsigned long long acc2[8][4];
#pragma unroll
    for (int r = 0; r < 8; r++)
#pragma unroll
        for (int p = 0; p < 4; p++) acc2[r][p] = 0ull;

    // ---- prologue ----------------------------------------------------------
    {
        float4 a0 = make_float4(0.f, 0.f, 0.f, 0.f), a1 = a0;
        if (larow < N) {
            a0 = *(const float4*)(A + (size_t)larow * 128 + la_k + 0);
            a1 = *(const float4*)(A + (size_t)larow * 128 + la_k + 4);
        }
        As[0][la_r][la_k + 0] = a0.x; As[0][la_r][la_k + 1] = a0.y;
        As[0][la_r][la_k + 2] = a0.z; As[0][la_r][la_k + 3] = a0.w;
        As[0][la_r][la_k + 4] = a1.x; As[0][la_r][la_k + 5] = a1.y;
        As[0][la_r][la_k + 6] = a1.z; As[0][la_r][la_k + 7] = a1.w;
        float4 b0 = *(const float4*)(W + (size_t)lb_k * 128 + lb_c + 0);
        float4 b1 = *(const float4*)(W + (size_t)lb_k * 128 + lb_c + 4);
        *(float4*)&Bs[0][lb_k][lb_c + 0] = b0;
        *(float4*)&Bs[0][lb_k][lb_c + 4] = b1;
    }
    __syncthreads();

    // ---- main loop: 8 chunks, ping-pong ------------------------------------
#pragma unroll
    for (int ch = 0; ch < 8; ch++) {
        const int cur = ch & 1;
        const int nxt = cur ^ 1;
        float4 pa0, pa1, pb0, pb1;
        if (ch < 7) {
            const int k0 = (ch + 1) * CHUNK;
            pa0 = make_float4(0.f, 0.f, 0.f, 0.f); pa1 = pa0;
            if (larow < N) {
                pa0 = *(const float4*)(A + (size_t)larow * 128 + k0 + la_k + 0);
                pa1 = *(const float4*)(A + (size_t)larow * 128 + k0 + la_k + 4);
            }
            pb0 = *(const float4*)(W + (size_t)(k0 + lb_k) * 128 + lb_c + 0);
            pb1 = *(const float4*)(W + (size_t)(k0 + lb_k) * 128 + lb_c + 4);
        }

#pragma unroll
        for (int kk = 0; kk < CHUNK; kk++) {
            unsigned long long b2[4];
#pragma unroll
            for (int p = 0; p < 4; p++)
                b2[p] = *(const unsigned long long*)&Bs[cur][kk][colt * 8 + p * 2];
#pragma unroll
            for (int r = 0; r < 8; r++) {
                unsigned long long a2 = pack2_dup(As[cur][rowt * 8 + r][kk]);
#pragma unroll
                for (int p = 0; p < 4; p++) fma2(acc2[r][p], a2, b2[p]);
            }
        }

        if (ch < 7) {
            As[nxt][la_r][la_k + 0] = pa0.x; As[nxt][la_r][la_k + 1] = pa0.y;
            As[nxt][la_r][la_k + 2] = pa0.z; As[nxt][la_r][la_k + 3] = pa0.w;
            As[nxt][la_r][la_k + 4] = pa1.x; As[nxt][la_r][la_k + 5] = pa1.y;
            As[nxt][la_r][la_k + 6] = pa1.z; As[nxt][la_r][la_k + 7] = pa1.w;
            *(float4*)&Bs[nxt][lb_k][lb_c + 0] = pb0;
            *(float4*)&Bs[nxt][lb_k][lb_c + 4] = pb1;
            __syncthreads();
        }
    }

    // ---- epilogue ----------------------------------------------------------
    float4 bv0 = make_float4(0.f, 0.f, 0.f, 0.f), bv1 = bv0;
    if (bias) {
        bv0 = *(const float4*)(bias + colt * 8 + 0);
        bv1 = *(const float4*)(bias + colt * 8 + 4);
    }
#pragma unroll
    for (int r = 0; r < 8; r++) {
        int grow = rowBase + rowt * 8 + r;
        if (grow >= N) continue;
        float sc = rowscale ? __ldg(&rowscale[grow]) : 1.0f;
        float* cp = C + (size_t)grow * 128 + colt * 8;
        float a0, a1, a2v, a3, a4, a5, a6, a7;
        unpack2(acc2[r][0], a0, a1);
        unpack2(acc2[r][1], a2v, a3);
        unpack2(acc2[r][2], a4, a5);
        unpack2(acc2[r][3], a6, a7);
        float4 v0, v1;
        v0.x = (a0 + bv0.x) * sc; v0.y = (a1 + bv0.y) * sc;
        v0.z = (a2v + bv0.z) * sc; v0.w = (a3 + bv0.w) * sc;
        v1.x = (a4 + bv1.x) * sc; v1.y = (a5 + bv1.y) * sc;
        v1.z = (a6 + bv1.z) * sc; v1.w = (a7 + bv1.w) * sc;
        *(float4*)(cp + 0) = v0;
        *(float4*)(cp + 4) = v1;
    }
}

// ---------------------------------------------------------------------------
// Gather (atomic-free GCN aggregate), fused self-loop + bias + tanh.
// Input h is already scaled by dinv[src] (GEMM epilogue).
//   out[d] = tanh( (h[d] + sum_{s in in(d)} h[s]) * dinv[d] + b )
// One warp per dst node; lane owns 4 feature floats. 8-wide MLP edge loop.
// ---------------------------------------------------------------------------
__global__ void gather_tanh(const float* __restrict__ h, const int* __restrict__ row_ptr,
                            const int* __restrict__ esrc, const float* __restrict__ dinv,
                            const float* __restrict__ b, float* __restrict__ out, int N) {
    int warp = (blockIdx.x * blockDim.x + threadIdx.x) >> 5;
    if (warp >= N) return;
    int lane = threadIdx.x & 31;

    const int beg = __ldg(&row_ptr[warp]);
    const int end = __ldg(&row_ptr[warp + 1]);
    const float di = __ldg(&dinv[warp]);

    float4 acc = *(const float4*)(h + (size_t)warp * 128 + lane * 4);

    int e = beg;
    for (; e + 7 < end; e += 8) {
        int s[8];
#pragma unroll
        for (int i = 0; i < 8; i++) s[i] = __ldg(&esrc[e + i]);
        float4 v[8];
#pragma unroll
        for (int i = 0; i < 8; i++)
            v[i] = *(const float4*)(h + (size_t)s[i] * 128 + lane * 4);
#pragma unroll
        for (int i = 0; i < 8; i++) {
            acc.x += v[i].x; acc.y += v[i].y; acc.z += v[i].z; acc.w += v[i].w;
        }
    }
    for (; e + 3 < end; e += 4) {
        int s[4];
#pragma unroll
        for (int i = 0; i < 4; i++) s[i] = __ldg(&esrc[e + i]);
        float4 v[4];
#pragma unroll
        for (int i = 0; i < 4; i++)
            v[i] = *(const float4*)(h + (size_t)s[i] * 128 + lane * 4);
#pragma unroll
        for (int i = 0; i < 4; i++) {
            acc.x += v[i].x; acc.y += v[i].y; acc.z += v[i].z; acc.w += v[i].w;
        }
    }
    for (; e < end; e++) {
        int s0 = __ldg(&esrc[e]);
        float4 v0 = *(const float4*)(h + (size_t)s0 * 128 + lane * 4);
        acc.x += v0.x; acc.y += v0.y; acc.z += v0.z; acc.w += v0.w;
    }

    const float4 bb = *(const float4*)(b + lane * 4);
    float4 o;
    o.x = tanhf(fmaf(acc.x, di, bb.x));
    o.y = tanhf(fmaf(acc.y, di, bb.y));
    o.z = tanhf(fmaf(acc.z, di, bb.z));
    o.w = tanhf(fmaf(acc.w, di, bb.w));
    *(float4*)(out + (size_t)warp * 128 + lane * 4) = o;
}

// ---------------------------------------------------------------------------
// Final: out[j] = max_n ( h[n] @ Wo[:,j] ) + bo[j],   Wo [128,64]
// ---------------------------------------------------------------------------
__device__ __forceinline__ void atomicMaxF(float* addr, float v) {
    if (v >= 0.f) atomicMax((int*)addr, __float_as_int(v));
    else          atomicMin((unsigned int*)addr, __float_as_uint(v));
}

__global__ void init_out(float* out, int n) {
    int i = blockIdx.x * blockDim.x + threadIdx.x;
    if (i < n) out[i] = -INFINITY;
}

__global__ void final_max(const float* __restrict__ h, const float* __restrict__ Wo,
                          const float* __restrict__ bo, float* __restrict__ out, int N) {
    int lane   = threadIdx.x & 31;
    int warpId = (blockIdx.x * blockDim.x + threadIdx.x) >> 5;
    int nwarps = (gridDim.x * blockDim.x) >> 5;
    float m0 = -INFINITY, m1 = -INFINITY;

    for (int base = warpId * 4; base < N; base += nwarps * 4) {
        float4 hr[4];
#pragma unroll
        for (int r = 0; r < 4; r++) {
            int n = base + r;
            if (n >= N) n = N - 1;  // duplicate is harmless under max
            hr[r] = *(const float4*)(h + (size_t)n * 128 + lane * 4);
        }
        float a[8];
#pragma unroll
        for (int i = 0; i < 8; i++) a[i] = 0.f;
#pragma unroll
        for (int l = 0; l < 32; l++) {
            float hb[4][4];
#pragma unroll
            for (int r = 0; r < 4; r++) {
                hb[r][0] = __shfl_sync(0xffffffffu, hr[r].x, l);
                hb[r][1] = __shfl_sync(0xffffffffu, hr[r].y, l);
                hb[r][2] = __shfl_sync(0xffffffffu, hr[r].z, l);
                hb[r][3] = __shfl_sync(0xffffffffu, hr[r].w, l);
            }
#pragma unroll
            for (int c = 0; c < 4; c++) {
                int k = l * 4 + c;
                float w0 = __ldg(&Wo[k * 64 + lane]);
                float w1 = __ldg(&Wo[k * 64 + lane + 32]);
#pragma unroll
                for (int r = 0; r < 4; r++) {
                    a[r]     = fmaf(hb[r][c], w0, a[r]);
                    a[4 + r] = fmaf(hb[r][c], w1, a[4 + r]);
                }
            }
        }
#pragma unroll
        for (int r = 0; r < 4; r++) {
            m0 = fmaxf(m0, a[r]);
            m1 = fmaxf(m1, a[4 + r]);
        }
    }
    m0 += __ldg(&bo[lane]);
    m1 += __ldg(&bo[lane + 32]);
    atomicMaxF(&out[lane], m0);
    atomicMaxF(&out[lane + 32], m1);
}

// ---------------------------------------------------------------------------
extern "C" void kernel_launch(void* const* d_in, const int* in_sizes, int n_in,
                              void* d_out, int out_size) {
    const float* x  = (const float*)d_in[0];
    const int*   ei = (const int*)  d_in[1];
    const float* W1 = (const float*)d_in[2];
    const float* b1 = (const float*)d_in[3];
    const float* Wl = (const float*)d_in[4];
    const float* bl = (const float*)d_in[5];
    const float* W2 = (const float*)d_in[6];
    const float* b2 = (const float*)d_in[7];
    const float* Wo = (const float*)d_in[8];
    const float* bo = (const float*)d_in[9];
    float* out = (float*)d_out;

    const int N = in_sizes[0] / 128;
    const int E = in_sizes[1] / 2;
    const int* src = ei;
    const int* dst = ei + E;

    float *U, *V, *dinv, *Wc, *bc;
    int *deg, *rowptr, *cursor, *esrc, *tilesum, *tileoff;
    cudaGetSymbolAddress((void**)&U,       g_U);
    cudaGetSymbolAddress((void**)&V,       g_V);
    cudaGetSymbolAddress((void**)&deg,     g_deg);
    cudaGetSymbolAddress((void**)&dinv,    g_dinv);
    cudaGetSymbolAddress((void**)&rowptr,  g_rowptr);
    cudaGetSymbolAddress((void**)&cursor,  g_cursor);
    cudaGetSymbolAddress((void**)&esrc,    g_esrc);
    cudaGetSymbolAddress((void**)&Wc,      g_Wc);
    cudaGetSymbolAddress((void**)&bc,      g_bc);
    cudaGetSymbolAddress((void**)&tilesum, g_tilesum);
    cudaGetSymbolAddress((void**)&tileoff, g_tileoff);

    const int T = 256;
    const int ntiles = (N + STILE - 1) / STILE;

    // ---- CSR build (parallel scan) + weight combine -------------------------
    zero_i<<<(N + T - 1) / T, T>>>(deg, N);
    deg_count<<<(E + T - 1) / T, T>>>(dst, E, deg);
    scan_local<<<ntiles, 256>>>(deg, rowptr, tilesum, N);
    scan_tiles<<<1, 64>>>(tilesum, tileoff, rowptr, ntiles, N);
    apply_off<<<(N + T - 1) / T, T>>>(rowptr, cursor, tileoff, deg, dinv, N);
    bucket_fill<<<(E + T - 1) / T, T>>>(src, dst, E, cursor, esrc);
    combine_w<<<FDIM + 1, FDIM>>>(Wl, bl, W2, Wc, bc);   // Wc = Wl@W2, bc = bl@W2

    const int gatherBlocks = (N * 32 + T - 1) / T;
    const int gemmBlocks = (N + 127) / 128;

    // ---- layer 1: U = (x @ W1) * dinv ; V = tanh(gather(U)*dinv + b1) -------
    gemm128<<<gemmBlocks, T>>>(x, W1, nullptr, dinv, U, N);
    gather_tanh<<<gatherBlocks, T>>>(U, rowptr, esrc, dinv, b1, V, N);

    // ---- fused linear+layer2 pre-GEMM: U = (V@Wc + bc) * dinv ---------------
    gemm128<<<gemmBlocks, T>>>(V, Wc, bc, dinv, U, N);
    gather_tanh<<<gatherBlocks, T>>>(U, rowptr, esrc, dinv, b2, V, N);

    // ---- output: out = max_n( V @ Wo ) + bo --------------------------------
    init_out<<<1, 64>>>(out, out_size);
    final_max<<<592, T>>>(V, Wo, bo, out, N);
}